// round 3
// baseline (speedup 1.0000x reference)
#include <cuda_runtime.h>
#include <cstdint>

// Problem constants
constexpr int B_   = 16;
constexpr int NH   = 64;
constexpr int NW   = 64;
constexpr int DO   = 768;
constexpr int KH   = 16;
constexpr int KW   = 16;
constexpr int H_   = 512;
constexpr int WF   = 512;

constexpr int M_ = B_ * NH * NW;   // 65536
constexpr int N_ = KH * KW;        // 256
constexpr int K_ = DO;             // 768

// GEMM tiling
constexpr int BM = 128, BN = 128, BK = 32;
constexpr int NTILES = K_ / BK;    // 24
constexpr int APAD = 36;           // padded smem row stride (floats)

// 64 MB scratch for proj, layout [b][h][dh][w][dw] = [16][64][16][64][16]
__device__ float g_proj[(size_t)M_ * N_];

__device__ __forceinline__ uint32_t f2tf32(float x) {
    uint32_t r;
    asm volatile("cvt.rna.tf32.f32 %0, %1;" : "=r"(r) : "f"(x));
    return r;
}

#define MMA_TF32(d, a, b)                                                         \
    asm volatile(                                                                 \
        "mma.sync.aligned.m16n8k8.row.col.f32.tf32.tf32.f32 "                     \
        "{%0,%1,%2,%3}, {%4,%5,%6,%7}, {%8,%9}, {%0,%1,%2,%3};\n"                 \
        : "+f"(d[0]), "+f"(d[1]), "+f"(d[2]), "+f"(d[3])                          \
        : "r"(a[0]), "r"(a[1]), "r"(a[2]), "r"(a[3]), "r"(b[0]), "r"(b[1]))

// proj = tgt[M,K] @ W[N,K]^T
__global__ __launch_bounds__(256) void gemm_tf32_kernel(
    const float* __restrict__ A, const float* __restrict__ Bw) {
    extern __shared__ float smem[];
    float* As = smem;                       // [2][128][APAD]
    float* Bs = smem + 2 * BM * APAD;       // [2][128][APAD]

    const int tid  = threadIdx.x;
    const int bN   = blockIdx.x * BN;       // N fastest -> A tile L2 reuse
    const int bM   = blockIdx.y * BM;

    const int warp = tid >> 5;
    const int lane = tid & 31;
    const int wM   = (warp & 1) * 64;       // warp tile 64x32
    const int wN   = (warp >> 1) * 32;
    const int grp  = lane >> 2;             // 0..7
    const int tig  = lane & 3;              // 0..3

    const int lrow = tid >> 3;              // 0..31
    const int lcol = (tid & 7) * 4;         // 0..28

    float4 ra[4], rb[4];

    auto load_tile = [&](int t) {
        const int k0 = t * BK;
        #pragma unroll
        for (int p = 0; p < 4; ++p) {
            const int r = p * 32 + lrow;
            ra[p] = *(const float4*)(A  + (size_t)(bM + r) * K_ + k0 + lcol);
            rb[p] = *(const float4*)(Bw + (size_t)(bN + r) * K_ + k0 + lcol);
        }
    };
    auto store_tile = [&](int buf) {
        float* as = As + buf * BM * APAD;
        float* bs = Bs + buf * BM * APAD;
        #pragma unroll
        for (int p = 0; p < 4; ++p) {
            const int r = p * 32 + lrow;
            float4 va = ra[p], vb = rb[p];
            va.x = __uint_as_float(f2tf32(va.x)); va.y = __uint_as_float(f2tf32(va.y));
            va.z = __uint_as_float(f2tf32(va.z)); va.w = __uint_as_float(f2tf32(va.w));
            vb.x = __uint_as_float(f2tf32(vb.x)); vb.y = __uint_as_float(f2tf32(vb.y));
            vb.z = __uint_as_float(f2tf32(vb.z)); vb.w = __uint_as_float(f2tf32(vb.w));
            *(float4*)(as + r * APAD + lcol) = va;
            *(float4*)(bs + r * APAD + lcol) = vb;
        }
    };

    float acc[4][4][4];
    #pragma unroll
    for (int i = 0; i < 4; ++i)
        #pragma unroll
        for (int j = 0; j < 4; ++j)
            #pragma unroll
            for (int r = 0; r < 4; ++r) acc[i][j][r] = 0.f;

    load_tile(0);
    store_tile(0);
    __syncthreads();

    for (int t = 0; t < NTILES; ++t) {
        const int buf = t & 1;
        if (t + 1 < NTILES) load_tile(t + 1);

        const float* as = As + buf * BM * APAD;
        const float* bs = Bs + buf * BM * APAD;
        #pragma unroll
        for (int kk = 0; kk < 4; ++kk) {
            const int k0 = kk * 8;
            uint32_t af[4][4], bf[4][2];
            #pragma unroll
            for (int i = 0; i < 4; ++i) {
                const float* p0 = as + (wM + i * 16 + grp) * APAD + k0 + tig;
                af[i][0] = __float_as_uint(p0[0]);
                af[i][2] = __float_as_uint(p0[4]);
                const float* p1 = p0 + 8 * APAD;
                af[i][1] = __float_as_uint(p1[0]);
                af[i][3] = __float_as_uint(p1[4]);
            }
            #pragma unroll
            for (int j = 0; j < 4; ++j) {
                const float* p0 = bs + (wN + j * 8 + grp) * APAD + k0 + tig;
                bf[j][0] = __float_as_uint(p0[0]);
                bf[j][1] = __float_as_uint(p0[4]);
            }
            #pragma unroll
            for (int i = 0; i < 4; ++i)
                #pragma unroll
                for (int j = 0; j < 4; ++j)
                    MMA_TF32(acc[i][j], af[i], bf[j]);
        }
        if (t + 1 < NTILES) store_tile(1 - buf);
        __syncthreads();
    }

    // epilogue: write proj in [b][h][dh][w][dw] layout
    //   m -> (b*64+h) = m>>6, w = m&63 ;  n -> dh = n>>4, dw = n&15
    //   off(m,n) = ((m>>6)*16 + dh)*1024 + (m&63)*16 + dw
    #pragma unroll
    for (int i = 0; i < 4; ++i) {
        const int r0 = bM + wM + i * 16 + grp;
        #pragma unroll
        for (int j = 0; j < 4; ++j) {
            const int c0 = bN + wN + j * 8 + tig * 2;   // even, dw<=14
            const int dh = c0 >> 4, dw = c0 & 15;
            const size_t o0 =
                (((size_t)(r0 >> 6) * 16 + dh) << 10) + ((r0 & 63) << 4) + dw;
            const size_t o1 =
                (((size_t)((r0 + 8) >> 6) * 16 + dh) << 10) + (((r0 + 8) & 63) << 4) + dw;
            *(float2*)(g_proj + o0) = make_float2(acc[i][j][0], acc[i][j][1]);
            *(float2*)(g_proj + o1) = make_float2(acc[i][j][2], acc[i][j][3]);
        }
    }
}

// fold: gather + mean from [b][h][dh][w][dw] layout
__global__ __launch_bounds__(256) void fold_kernel(float* __restrict__ out) {
    const int flat = blockIdx.x * blockDim.x + threadIdx.x;
    if (flat >= B_ * H_ * WF) return;
    const int b   = flat >> 18;
    const int rem = flat & (H_ * WF - 1);
    const int y   = rem >> 9;
    const int x   = rem & (WF - 1);

    int ry[10]; int cy = 0;            // ry = h*16 + dh
    {
        const int Y = y >> 3, py = y & 7;
        ry[cy++] = Y * 16 + py;
        if (Y > 0) ry[cy++] = (Y - 1) * 16 + py + 8;
        if (y == H_ - 1) {
            #pragma unroll
            for (int d = 8; d <= 15; ++d) ry[cy++] = (NH - 1) * 16 + d;
        }
    }
    int rx[10]; int cx = 0;            // rx = w*16 + dw
    {
        const int X = x >> 3, px = x & 7;
        rx[cx++] = X * 16 + px;
        if (X > 0) rx[cx++] = (X - 1) * 16 + px + 8;
        if (x == WF - 1) {
            #pragma unroll
            for (int d = 8; d <= 15; ++d) rx[cx++] = (NW - 1) * 16 + d;
        }
    }

    const float* pb = g_proj + ((size_t)b << 20);   // b * 64*16*64*16
    float s = 0.f;
    for (int i = 0; i < cy; ++i) {
        const float* prow = pb + ((size_t)ry[i] << 10);
        for (int j = 0; j < cx; ++j)
            s += prow[rx[j]];
    }
    out[flat] = s * (1.0f / (float)(cy * cx));
}

extern "C" void kernel_launch(void* const* d_in, const int* in_sizes, int n_in,
                              void* d_out, int out_size) {
    const float* tgt    = (const float*)d_in[0];   // [16, 4096, 768]
    const float* weight = (const float*)d_in[1];   // [16, 16, 768] -> [256, 768]
    float* out = (float*)d_out;                    // [16, 512, 512]

    const int smem_bytes = 2 * 2 * BM * APAD * (int)sizeof(float);  // 73728
    cudaFuncSetAttribute(gemm_tf32_kernel,
                         cudaFuncAttributeMaxDynamicSharedMemorySize, smem_bytes);

    dim3 grid(N_ / BN, M_ / BM);   // (2, 512)
    gemm_tf32_kernel<<<grid, 256, smem_bytes>>>(tgt, weight);

    const int total = B_ * H_ * WF;
    fold_kernel<<<(total + 255) / 256, 256>>>(out);
}

// round 4
// speedup vs baseline: 1.1432x; 1.1432x over previous
#include <cuda_runtime.h>
#include <cstdint>

// Problem constants
constexpr int B_   = 16;
constexpr int NH   = 64;
constexpr int NW   = 64;
constexpr int DO   = 768;
constexpr int KH   = 16;
constexpr int KW   = 16;
constexpr int H_   = 512;
constexpr int WF   = 512;

constexpr int M_ = B_ * NH * NW;   // 65536
constexpr int N_ = KH * KW;        // 256
constexpr int K_ = DO;             // 768

// GEMM tiling
constexpr int BM = 128, BN = 128, BK = 32;
constexpr int NTILES = K_ / BK;    // 24
constexpr int APAD = 36;

// 64 MB scratch: proj[m][n], m = ((b*64+h)*64+w), n = dh*16+dw
__device__ float g_proj[(size_t)M_ * N_];

__device__ __forceinline__ uint32_t f2tf32(float x) {
    uint32_t r;
    asm volatile("cvt.rna.tf32.f32 %0, %1;" : "=r"(r) : "f"(x));
    return r;
}

#define MMA_TF32(d, a, b)                                                         \
    asm volatile(                                                                 \
        "mma.sync.aligned.m16n8k8.row.col.f32.tf32.tf32.f32 "                     \
        "{%0,%1,%2,%3}, {%4,%5,%6,%7}, {%8,%9}, {%0,%1,%2,%3};\n"                 \
        : "+f"(d[0]), "+f"(d[1]), "+f"(d[2]), "+f"(d[3])                          \
        : "r"(a[0]), "r"(a[1]), "r"(a[2]), "r"(a[3]), "r"(b[0]), "r"(b[1]))

// proj = tgt[M,K] @ W[N,K]^T
__global__ __launch_bounds__(256) void gemm_tf32_kernel(
    const float* __restrict__ A, const float* __restrict__ Bw) {
    extern __shared__ float smem[];
    float* As = smem;                       // [2][128][APAD]
    float* Bs = smem + 2 * BM * APAD;       // [2][128][APAD]

    const int tid  = threadIdx.x;
    const int bN   = blockIdx.x * BN;
    const int bM   = blockIdx.y * BM;

    const int warp = tid >> 5;
    const int lane = tid & 31;
    const int wM   = (warp & 1) * 64;
    const int wN   = (warp >> 1) * 32;
    const int grp  = lane >> 2;
    const int tig  = lane & 3;

    const int lrow = tid >> 3;
    const int lcol = (tid & 7) * 4;

    float4 ra[4], rb[4];

    auto load_tile = [&](int t) {
        const int k0 = t * BK;
        #pragma unroll
        for (int p = 0; p < 4; ++p) {
            const int r = p * 32 + lrow;
            ra[p] = *(const float4*)(A  + (size_t)(bM + r) * K_ + k0 + lcol);
            rb[p] = *(const float4*)(Bw + (size_t)(bN + r) * K_ + k0 + lcol);
        }
    };
    auto store_tile = [&](int buf) {
        float* as = As + buf * BM * APAD;
        float* bs = Bs + buf * BM * APAD;
        #pragma unroll
        for (int p = 0; p < 4; ++p) {
            const int r = p * 32 + lrow;
            float4 va = ra[p], vb = rb[p];
            va.x = __uint_as_float(f2tf32(va.x)); va.y = __uint_as_float(f2tf32(va.y));
            va.z = __uint_as_float(f2tf32(va.z)); va.w = __uint_as_float(f2tf32(va.w));
            vb.x = __uint_as_float(f2tf32(vb.x)); vb.y = __uint_as_float(f2tf32(vb.y));
            vb.z = __uint_as_float(f2tf32(vb.z)); vb.w = __uint_as_float(f2tf32(vb.w));
            *(float4*)(as + r * APAD + lcol) = va;
            *(float4*)(bs + r * APAD + lcol) = vb;
        }
    };

    float acc[4][4][4];
    #pragma unroll
    for (int i = 0; i < 4; ++i)
        #pragma unroll
        for (int j = 0; j < 4; ++j)
            #pragma unroll
            for (int r = 0; r < 4; ++r) acc[i][j][r] = 0.f;

    load_tile(0);
    store_tile(0);
    __syncthreads();

    for (int t = 0; t < NTILES; ++t) {
        const int buf = t & 1;
        if (t + 1 < NTILES) load_tile(t + 1);

        const float* as = As + buf * BM * APAD;
        const float* bs = Bs + buf * BM * APAD;
        #pragma unroll
        for (int kk = 0; kk < 4; ++kk) {
            const int k0 = kk * 8;
            uint32_t af[4][4], bf[4][2];
            #pragma unroll
            for (int i = 0; i < 4; ++i) {
                const float* p0 = as + (wM + i * 16 + grp) * APAD + k0 + tig;
                af[i][0] = __float_as_uint(p0[0]);
                af[i][2] = __float_as_uint(p0[4]);
                const float* p1 = p0 + 8 * APAD;
                af[i][1] = __float_as_uint(p1[0]);
                af[i][3] = __float_as_uint(p1[4]);
            }
            #pragma unroll
            for (int j = 0; j < 4; ++j) {
                const float* p0 = bs + (wN + j * 8 + grp) * APAD + k0 + tig;
                bf[j][0] = __float_as_uint(p0[0]);
                bf[j][1] = __float_as_uint(p0[4]);
            }
            #pragma unroll
            for (int i = 0; i < 4; ++i)
                #pragma unroll
                for (int j = 0; j < 4; ++j)
                    MMA_TF32(acc[i][j], af[i], bf[j]);
        }
        if (t + 1 < NTILES) store_tile(1 - buf);
        __syncthreads();
    }

    // epilogue: contiguous [m][n] stores (fully coalesced)
    #pragma unroll
    for (int i = 0; i < 4; ++i) {
        const int r0 = bM + wM + i * 16 + grp;
        #pragma unroll
        for (int j = 0; j < 4; ++j) {
            const int c0 = bN + wN + j * 8 + tig * 2;
            *(float2*)(g_proj + (size_t)r0 * N_ + c0) =
                make_float2(acc[i][j][0], acc[i][j][1]);
            *(float2*)(g_proj + (size_t)(r0 + 8) * N_ + c0) =
                make_float2(acc[i][j][2], acc[i][j][3]);
        }
    }
}

// ---------------- fold ----------------
// Generic scalar path for edge pixels (y==511 row, x==511 column).
__device__ __noinline__ float fold_pix(const float* __restrict__ pb, int y, int x) {
    int hy[10], dy[10]; int cy = 0;
    {
        const int Y = y >> 3, py = y & 7;
        hy[cy] = Y; dy[cy] = py; ++cy;
        if (Y > 0) { hy[cy] = Y - 1; dy[cy] = py + 8; ++cy; }
        if (y == H_ - 1)
            for (int d = 8; d <= 15; ++d) { hy[cy] = NH - 1; dy[cy] = d; ++cy; }
    }
    int hx[10], dx[10]; int cx = 0;
    {
        const int X = x >> 3, px = x & 7;
        hx[cx] = X; dx[cx] = px; ++cx;
        if (X > 0) { hx[cx] = X - 1; dx[cx] = px + 8; ++cx; }
        if (x == WF - 1)
            for (int d = 8; d <= 15; ++d) { hx[cx] = NW - 1; dx[cx] = d; ++cx; }
    }
    float s = 0.f;
    for (int i = 0; i < cy; ++i) {
        const float* r = pb + ((size_t)(hy[i] * 64) << 8) + dy[i] * 16;
        for (int j = 0; j < cx; ++j)
            s += r[(hx[j] << 8) + dx[j]];
    }
    return s / (float)(cy * cx);
}

// One thread per 4 consecutive x pixels; interior path is branch-light,
// at most 4 aligned float4 loads.
__global__ __launch_bounds__(256) void fold_kernel(float* __restrict__ out) {
    const int t   = blockIdx.x * blockDim.x + threadIdx.x;   // 1,048,576 threads
    const int b   = t >> 16;
    const int rem = t & 65535;
    const int y   = rem >> 7;          // 0..511
    const int xq  = rem & 127;         // x0 = xq*4
    const int x0  = xq << 2;

    const float* pb = g_proj + ((size_t)b << 20);            // b * 4096 * 256
    float* op = out + ((size_t)b << 18) + (y << 9) + x0;

    if (y == H_ - 1 || xq == 127) {    // edge fallback (0.4% of threads)
        float4 s;
        s.x = fold_pix(pb, y, x0);
        s.y = fold_pix(pb, y, x0 + 1);
        s.z = fold_pix(pb, y, x0 + 2);
        s.w = fold_pix(pb, y, x0 + 3);
        *(float4*)op = s;
        return;
    }

    const int Y = y >> 3, py = y & 7;
    const int X = x0 >> 3, px = x0 & 7;        // px in {0,4}
    // base points at proj[(b,Y,X)][py*16+px]
    const float* prow = pb + ((size_t)(Y * 64 + X) << 8) + py * 16 + px;

    float4 s = *(const float4*)prow;           // (Y, X)
    if (X > 0) {                                // (Y, X-1): m-1, n+8
        float4 v = *(const float4*)(prow - 248);
        s.x += v.x; s.y += v.y; s.z += v.z; s.w += v.w;
    }
    if (Y > 0) {                                // (Y-1, X): m-64, n+128
        const float* pu = prow - 16384 + 128;
        float4 v = *(const float4*)pu;
        s.x += v.x; s.y += v.y; s.z += v.z; s.w += v.w;
        if (X > 0) {                            // (Y-1, X-1)
            float4 w = *(const float4*)(pu - 248);
            s.x += w.x; s.y += w.y; s.z += w.z; s.w += w.w;
        }
    }
    const float inv = 1.0f /
        (float)((1 + (X > 0 ? 1 : 0)) * (1 + (Y > 0 ? 1 : 0)));
    s.x *= inv; s.y *= inv; s.z *= inv; s.w *= inv;
    *(float4*)op = s;
}

extern "C" void kernel_launch(void* const* d_in, const int* in_sizes, int n_in,
                              void* d_out, int out_size) {
    const float* tgt    = (const float*)d_in[0];   // [16, 4096, 768]
    const float* weight = (const float*)d_in[1];   // [256, 768]
    float* out = (float*)d_out;                    // [16, 512, 512]

    const int smem_bytes = 2 * 2 * BM * APAD * (int)sizeof(float);  // 73728
    cudaFuncSetAttribute(gemm_tf32_kernel,
                         cudaFuncAttributeMaxDynamicSharedMemorySize, smem_bytes);

    dim3 grid(N_ / BN, M_ / BM);   // (2, 512)
    gemm_tf32_kernel<<<grid, 256, smem_bytes>>>(tgt, weight);

    const int nthreads = B_ * H_ * WF / 4;         // 1,048,576
    fold_kernel<<<nthreads / 256, 256>>>(out);
}